// round 1
// baseline (speedup 1.0000x reference)
#include <cuda_runtime.h>
#include <cuda_bf16.h>

#define RED_BLOCKS 1184          // 148 SMs * 8
#define RED_THREADS 256

__device__ float g_partials[RED_BLOCKS];

__global__ void __launch_bounds__(RED_THREADS)
qsum_partial_kernel(const float* __restrict__ phi,
                    const float* __restrict__ w,
                    int n)
{
    const int n4 = n >> 2;
    const float4* __restrict__ p4 = reinterpret_cast<const float4*>(phi);
    const float4* __restrict__ w4 = reinterpret_cast<const float4*>(w);

    float acc = 0.0f;
    const int stride = gridDim.x * blockDim.x;
    for (int i = blockIdx.x * blockDim.x + threadIdx.x; i < n4; i += stride) {
        float4 p = p4[i];
        float4 q = w4[i];
        acc += __cosf(p.x * q.x);
        acc += __cosf(p.y * q.y);
        acc += __cosf(p.z * q.z);
        acc += __cosf(p.w * q.w);
    }

    // scalar tail (n % 4 elements), handled by the first few global threads
    int tail = n - (n4 << 2);
    int gtid = blockIdx.x * blockDim.x + threadIdx.x;
    if (gtid < tail) {
        int idx = (n4 << 2) + gtid;
        acc += __cosf(phi[idx] * w[idx]);
    }

    // warp reduce
    #pragma unroll
    for (int off = 16; off > 0; off >>= 1)
        acc += __shfl_down_sync(0xFFFFFFFFu, acc, off);

    __shared__ float s_warp[RED_THREADS / 32];
    int lane = threadIdx.x & 31;
    int wid  = threadIdx.x >> 5;
    if (lane == 0) s_warp[wid] = acc;
    __syncthreads();

    if (wid == 0) {
        float v = (lane < RED_THREADS / 32) ? s_warp[lane] : 0.0f;
        #pragma unroll
        for (int off = 4; off > 0; off >>= 1)
            v += __shfl_down_sync(0xFFFFFFFFu, v, off);
        if (lane == 0) g_partials[blockIdx.x] = v;
    }
}

__global__ void __launch_bounds__(1024)
qsum_final_kernel(float* __restrict__ out, int nblocks,
                  float add_const, float inv_m)
{
    // single block, deterministic tree reduce of block partials in double
    __shared__ double s_red[1024];
    double v = 0.0;
    for (int i = threadIdx.x; i < nblocks; i += 1024)
        v += (double)g_partials[i];
    s_red[threadIdx.x] = v;
    __syncthreads();
    for (int off = 512; off > 0; off >>= 1) {
        if (threadIdx.x < off) s_red[threadIdx.x] += s_red[threadIdx.x + off];
        __syncthreads();
    }
    if (threadIdx.x == 0)
        out[0] = (float)((s_red[0] + (double)add_const) * (double)inv_m);
}

extern "C" void kernel_launch(void* const* d_in, const int* in_sizes, int n_in,
                              void* d_out, int out_size)
{
    const float* phi = (const float*)d_in[0];
    const float* w   = (const float*)d_in[1];
    float* out = (float*)d_out;
    int n = in_sizes[0];

    // M = next power of two >= n
    long long M = 1;
    while (M < (long long)n) M <<= 1;
    float add_const = (float)(M - (long long)n);
    float inv_m = (float)(1.0 / (double)M);

    int blocks = RED_BLOCKS;
    long long work4 = (n >> 2);
    if (work4 < (long long)blocks * RED_THREADS) {
        blocks = (int)((work4 + RED_THREADS - 1) / RED_THREADS);
        if (blocks < 1) blocks = 1;
    }

    qsum_partial_kernel<<<blocks, RED_THREADS>>>(phi, w, n);
    qsum_final_kernel<<<1, 1024>>>(out, blocks, add_const, inv_m);
}